// round 14
// baseline (speedup 1.0000x reference)
#include <cuda_runtime.h>
#include <cuda_bf16.h>
#include <cstdint>

#define NN 8192
#define CC 128

#if defined(__CUDA_ARCH_FEAT_SM103_ALL) || defined(__CUDA_ARCH_FEAT_SM100_ALL) || defined(__CUDA_ARCH_FEAT_SM101_ALL)
#define HAS_TCGEN05 1
#else
#define HAS_TCGEN05 0
#endif

// ---------------- scratch (__device__ globals: allocation-free rule) --------
__device__ float g_T1[NN * CC];
__device__ float g_P[2 * NN * CC];                 // split-K partials
__device__ __nv_bfloat16 g_Bt_hi[CC * NN];         // transposed B operand, hi
__device__ __nv_bfloat16 g_Bt_lo[CC * NN];         // transposed B operand, lo

// ---------------- PTX helpers (safe on all targets) -------------------------
__device__ __forceinline__ uint32_t smem_u32(const void* p) {
    uint32_t a;
    asm("{ .reg .u64 t; cvta.to.shared.u64 t, %1; cvt.u32.u64 %0, t; }" : "=r"(a) : "l"(p));
    return a;
}

#define MBARRIER_INIT(addr, cnt) \
    asm volatile("mbarrier.init.shared.b64 [%0], %1;" :: "r"((uint32_t)(addr)), "r"((uint32_t)(cnt)) : "memory")

#define MBARRIER_ARRIVE(addr) \
    asm volatile("mbarrier.arrive.release.cta.shared::cta.b64 _, [%0];" :: "r"((uint32_t)(addr)) : "memory")

#define MBARRIER_WAIT_PARITY(addr, parity) do {                                    \
    uint32_t _m = (uint32_t)(addr), _p = (uint32_t)(parity), _d;                   \
    asm volatile("{\n\t.reg .pred p;\n\t"                                          \
        "mbarrier.try_wait.parity.acquire.cta.shared::cta.b64 p, [%1], %2;\n\t"    \
        "selp.b32 %0, 1, 0, p;\n\t}" : "=r"(_d) : "r"(_m), "r"(_p) : "memory");    \
    if (!_d) {                                                                     \
        asm volatile("{\n\t.reg .pred P1;\n\t"                                     \
            "WL_%=:\n\t"                                                           \
            "mbarrier.try_wait.parity.acquire.cta.shared::cta.b64 P1, [%0], %1, 0x989680;\n\t" \
            "@P1 bra.uni WD_%=;\n\tbra.uni WL_%=;\n\tWD_%=:\n\t}"                  \
            :: "r"(_m), "r"(_p) : "memory");                                       \
    }                                                                              \
} while (0)

#define FENCE_PROXY_ASYNC()    asm volatile("fence.proxy.async.shared::cta;" ::: "memory")

// SW128 descriptor: layout=2, version=1, SBO=64, LBO=1
static constexpr uint64_t DESC_BASE_SW128 =
    (uint64_t(2) << 61) | (uint64_t(1) << 46) | (uint64_t(64) << 32) | (uint64_t(1) << 16);
#define MAKE_DESC(addr) (DESC_BASE_SW128 | ((uint64_t)((addr) >> 4) & 0x3FFF))

__device__ __forceinline__ uint32_t sw128(uint32_t o) { return o ^ ((o >> 3) & 0x70); }

// paired fp32->bf16 convert: returns {bf16(hi_src) , bf16(lo_src)} packed
__device__ __forceinline__ uint32_t cvt_bf16x2(float hi_src, float lo_src) {
    uint32_t r;
    asm("cvt.rn.bf16x2.f32 %0, %1, %2;" : "=r"(r) : "f"(hi_src), "f"(lo_src));
    return r;
}

// idesc: fp32 accum, bf16 A/B, M=128, N=128
static constexpr uint32_t IDESC =
    (1u << 4) | (1u << 7) | (1u << 10) | ((128u / 8) << 17) | ((128u / 16) << 24);

// ---------------- smem layout ------------------------------------------------
// [0] tmem ptr | [16,40) full[3] | [40,88) empty[3][2] | [88,96) done
// [1024+) 3 stages x (A_hi 16K | A_lo 16K | B_hi 16K | B_lo 16K)
#define SM_TMEM   0
#define SM_FULL   16
#define SM_EMPTY  40
#define SM_DONE   88
#define SM_TILES  1024
#define STAGE_SZ  65536
#define NSTAGE    3
#define SMEM_TOTAL (SM_TILES + NSTAGE * STAGE_SZ)

// ---------------- tensor-core GEMM: P[khalf] = L[tile] @ Bt^T ----------------
// grid (64, 2); 544 threads. Warps 0-7 fill EVEN chunks, warps 8-15 ODD chunks.
// Distance-2-chunk software pipeline: at chunk c, B(c+2) is issued and A(c+2)
// is loaded to registers, so all global latency is hidden by a full iteration.
__global__ __launch_bounds__(544, 1)
void gemm_tc(const float* __restrict__ L,
             const __nv_bfloat16* __restrict__ Bhi,
             const __nv_bfloat16* __restrict__ Blo,
             float* __restrict__ P)
{
#if HAS_TCGEN05
    extern __shared__ char smem[];
    const uint32_t sbase = smem_u32(smem);
    const int tid = threadIdx.x;
    const int wid = tid >> 5, lid = tid & 31;
    const int mBase = blockIdx.x * 128;
    const int khalf = blockIdx.y;
    const int kStart = khalf * 4096;
    const int NCHUNK = 4096 / 64;

    if (wid == 0)
        asm volatile("tcgen05.alloc.cta_group::1.sync.aligned.shared::cta.b32 [%0], %1;"
                     :: "r"(sbase + SM_TMEM), "r"(128u) : "memory");
    if (tid == 0) {
#pragma unroll
        for (int s = 0; s < NSTAGE; s++) {
            MBARRIER_INIT(sbase + SM_FULL + 8 * s, 8);              // 8 warps per filling group
            MBARRIER_INIT(sbase + SM_EMPTY + 16 * s + 0, 1);        // empty[s][g=0]
            MBARRIER_INIT(sbase + SM_EMPTY + 16 * s + 8, 1);        // empty[s][g=1]
        }
        MBARRIER_INIT(sbase + SM_DONE, 1);
    }
    __syncthreads();
    uint32_t tmem;
    asm volatile("ld.shared.b32 %0, [%1];" : "=r"(tmem) : "r"(sbase + SM_TMEM));

    if (wid < 16) {
        // ---------------- producers: group g fills chunks c ≡ g (mod 2) ------
        const int g = (tid >> 8) & 1;            // warps 0-7 -> g=0, 8-15 -> g=1
        const int p = tid & 255;                 // 0..255 within group
        int phE[NSTAGE] = {0, 0, 0};

        // hoisted per-thread addressing
        const int aRow = p >> 4, aCol = p & 15;          // A: rows aRow+16i, float4 col aCol
        const int bRow = p >> 3, bCol = p & 7;           // B: rows bRow+32i, 16B col bCol
        const float* aBase = L + (size_t)(mBase + aRow) * NN + kStart + aCol * 4;
        const __nv_bfloat16* bhBase = Bhi + (size_t)bRow * NN + kStart + bCol * 8;
        const __nv_bfloat16* blBase = Blo + (size_t)bRow * NN + kStart + bCol * 8;
        uint32_t aOff[8], bOff[4];
#pragma unroll
        for (int i = 0; i < 8; i++) aOff[i] = sw128((uint32_t)((aRow + 16 * i) * 128 + aCol * 8));
#pragma unroll
        for (int i = 0; i < 4; i++) bOff[i] = sw128((uint32_t)((bRow + 32 * i) * 128 + bCol * 16));

        // prologue: chunk c0 = g — issue B(c0), load A(c0)
        float4 va[8];
        {
            const int s0 = g;                     // g%3
            const uint32_t stg = sbase + SM_TILES + s0 * STAGE_SZ;
            const int kOff = g * 64;
#pragma unroll
            for (int i = 0; i < 4; i++) {
                asm volatile("cp.async.cg.shared.global [%0], [%1], 16;"
                             :: "r"(stg + 32768 + bOff[i]), "l"(bhBase + (size_t)(32 * i) * NN + kOff) : "memory");
                asm volatile("cp.async.cg.shared.global [%0], [%1], 16;"
                             :: "r"(stg + 49152 + bOff[i]), "l"(blBase + (size_t)(32 * i) * NN + kOff) : "memory");
            }
            asm volatile("cp.async.commit_group;" ::: "memory");
#pragma unroll
            for (int i = 0; i < 8; i++)
                va[i] = *(const float4*)(aBase + (size_t)(16 * i) * NN + kOff);
        }

        for (int j = 0; j < NCHUNK / 2; j++) {
            const int c = 2 * j + g;
            const int s = c % 3;
            char* stgp = smem + SM_TILES + s * STAGE_SZ;
            const int cn = c + 2;

            // ---- issue B(c+2) into its stage (after that stage's empty-wait)
            if (cn < NCHUNK) {
                const int sn = cn % 3;
                if (cn >= 3) { MBARRIER_WAIT_PARITY(sbase + SM_EMPTY + 16 * sn + 8 * g, phE[sn]); phE[sn] ^= 1; }
                const uint32_t stgN = sbase + SM_TILES + sn * STAGE_SZ;
                const int kOffN = cn * 64;
#pragma unroll
                for (int i = 0; i < 4; i++) {
                    asm volatile("cp.async.cg.shared.global [%0], [%1], 16;"
                                 :: "r"(stgN + 32768 + bOff[i]), "l"(bhBase + (size_t)(32 * i) * NN + kOffN) : "memory");
                    asm volatile("cp.async.cg.shared.global [%0], [%1], 16;"
                                 :: "r"(stgN + 49152 + bOff[i]), "l"(blBase + (size_t)(32 * i) * NN + kOffN) : "memory");
                }
                asm volatile("cp.async.commit_group;" ::: "memory");
            }

            // ---- convert + store A(c) from registers (paired cvt split) -----
#pragma unroll
            for (int i = 0; i < 8; i++) {
                float4 v = va[i];
                uint2 hp, lp;
                hp.x = cvt_bf16x2(v.y, v.x);
                hp.y = cvt_bf16x2(v.w, v.z);
                float h0 = __uint_as_float(hp.x << 16);
                float h1 = __uint_as_float(hp.x & 0xFFFF0000u);
                float h2 = __uint_as_float(hp.y << 16);
                float h3 = __uint_as_float(hp.y & 0xFFFF0000u);
                lp.x = cvt_bf16x2(v.y - h1, v.x - h0);
                lp.y = cvt_bf16x2(v.w - h3, v.z - h2);
                *(uint2*)(stgp + aOff[i]) = hp;             // A_hi
                *(uint2*)(stgp + 16384 + aOff[i]) = lp;     // A_lo
            }

            // ---- prefetch A(c+2) into freed registers -----------------------
            if (cn < NCHUNK) {
                const int kOffN = cn * 64;
#pragma unroll
                for (int i = 0; i < 8; i++)
                    va[i] = *(const float4*)(aBase + (size_t)(16 * i) * NN + kOffN);
            }

            // ---- B(c) complete (B(c+2) stays in flight), publish stage s ----
            if (cn < NCHUNK)
                asm volatile("cp.async.wait_group 1;" ::: "memory");
            else
                asm volatile("cp.async.wait_group 0;" ::: "memory");
            __syncwarp();
            if (lid == 0) MBARRIER_ARRIVE(sbase + SM_FULL + 8 * s);
        }
    } else if (lid == 0) {
        // ---------------- MMA issuer (warp 16, lane 0) -----------------------
        int phF[NSTAGE] = {0, 0, 0};
        for (int c = 0; c < NCHUNK; c++) {
            const int s = c % 3;
            MBARRIER_WAIT_PARITY(sbase + SM_FULL + 8 * s, phF[s]);
            phF[s] ^= 1;
            FENCE_PROXY_ASYNC();
            const uint32_t stg = sbase + SM_TILES + s * STAGE_SZ;
            uint64_t dAh = MAKE_DESC(stg);
            uint64_t dAl = MAKE_DESC(stg + 16384);
            uint64_t dBh = MAKE_DESC(stg + 32768);
            uint64_t dBl = MAKE_DESC(stg + 49152);
#pragma unroll
            for (int ks = 0; ks < 4; ks++) {
                uint32_t en = (c > 0 || ks > 0) ? 1u : 0u;
                asm volatile(
                    "{\n\t.reg .pred p;\n\tsetp.ne.u32 p, %5, 0;\n\t"
                    "tcgen05.mma.cta_group::1.kind::f16 [%0], %1, %2, %3, {%4,%4,%4,%4}, p;\n\t}"
                    :: "r"(tmem), "l"(dAh + ks * 2), "l"(dBh + ks * 2), "r"(IDESC), "r"(0u), "r"(en) : "memory");
            }
#pragma unroll
            for (int ks = 0; ks < 4; ks++)
                asm volatile(
                    "{\n\t.reg .pred p;\n\tsetp.ne.u32 p, %5, 0;\n\t"
                    "tcgen05.mma.cta_group::1.kind::f16 [%0], %1, %2, %3, {%4,%4,%4,%4}, p;\n\t}"
                    :: "r"(tmem), "l"(dAh + ks * 2), "l"(dBl + ks * 2), "r"(IDESC), "r"(0u), "r"(1u) : "memory");
#pragma unroll
            for (int ks = 0; ks < 4; ks++)
                asm volatile(
                    "{\n\t.reg .pred p;\n\tsetp.ne.u32 p, %5, 0;\n\t"
                    "tcgen05.mma.cta_group::1.kind::f16 [%0], %1, %2, %3, {%4,%4,%4,%4}, p;\n\t}"
                    :: "r"(tmem), "l"(dAl + ks * 2), "l"(dBh + ks * 2), "r"(IDESC), "r"(0u), "r"(1u) : "memory");
            // stage s is next filled by chunk c+3 (group (c+1)&1)
            asm volatile("tcgen05.commit.cta_group::1.mbarrier::arrive::one.shared::cluster.b64 [%0];"
                         :: "r"(sbase + SM_EMPTY + 16 * s + 8 * ((c + 1) & 1)) : "memory");
        }
        asm volatile("tcgen05.commit.cta_group::1.mbarrier::arrive::one.shared::cluster.b64 [%0];"
                     :: "r"(sbase + SM_DONE) : "memory");
    }

    // all threads: wait for full completion
    MBARRIER_WAIT_PARITY(sbase + SM_DONE, 0);
    asm volatile("tcgen05.fence::after_thread_sync;" ::: "memory");

    // epilogue: warps 0-3 read subpartitions (128 rows x 128 fp32 cols)
    if (wid < 4) {
        const int m = mBase + wid * 32 + lid;
        float* dst = P + (size_t)khalf * NN * CC + (size_t)m * CC;
#pragma unroll
        for (int cb = 0; cb < 128; cb += 32) {
            uint32_t r[32];
            asm volatile("tcgen05.ld.sync.aligned.32x32b.x32.b32 "
                "{%0,%1,%2,%3,%4,%5,%6,%7,%8,%9,%10,%11,%12,%13,%14,%15,"
                "%16,%17,%18,%19,%20,%21,%22,%23,%24,%25,%26,%27,%28,%29,%30,%31}, [%32];"
                : "=r"(r[0]),"=r"(r[1]),"=r"(r[2]),"=r"(r[3]),"=r"(r[4]),"=r"(r[5]),"=r"(r[6]),"=r"(r[7]),
                  "=r"(r[8]),"=r"(r[9]),"=r"(r[10]),"=r"(r[11]),"=r"(r[12]),"=r"(r[13]),"=r"(r[14]),"=r"(r[15]),
                  "=r"(r[16]),"=r"(r[17]),"=r"(r[18]),"=r"(r[19]),"=r"(r[20]),"=r"(r[21]),"=r"(r[22]),"=r"(r[23]),
                  "=r"(r[24]),"=r"(r[25]),"=r"(r[26]),"=r"(r[27]),"=r"(r[28]),"=r"(r[29]),"=r"(r[30]),"=r"(r[31])
                : "r"(tmem + cb));
            asm volatile("tcgen05.wait::ld.sync.aligned;" ::: "memory");
#pragma unroll
            for (int j = 0; j < 32; j += 4) {
                float4 v = { __uint_as_float(r[j]), __uint_as_float(r[j + 1]),
                             __uint_as_float(r[j + 2]), __uint_as_float(r[j + 3]) };
                *(float4*)(dst + cb + j) = v;
            }
        }
        asm volatile("tcgen05.fence::before_thread_sync;" ::: "memory");
    }
    __syncthreads();
    if (wid == 0) {
        asm volatile("tcgen05.relinquish_alloc_permit.cta_group::1.sync.aligned;");
        asm volatile("tcgen05.dealloc.cta_group::1.sync.aligned.b32 %0, %1;" :: "r"(tmem), "r"(128u));
    }
#else
    // Fallback for the non-'a' PTX pass (never executed on GB300).
    const int tid = threadIdx.x;
    const int mBase = blockIdx.x * 128;
    const int khalf = blockIdx.y;
    const int kStart = khalf * 4096;
    for (int e = tid; e < 128 * 128; e += 544) {
        int m = mBase + (e >> 7), c = e & 127;
        float acc = 0.0f;
        const float* Lr = L + (size_t)m * NN + kStart;
        const __nv_bfloat16* bh = Bhi + (size_t)c * NN + kStart;
        const __nv_bfloat16* bl = Blo + (size_t)c * NN + kStart;
        for (int k = 0; k < 4096; k++)
            acc += Lr[k] * (__bfloat162float(bh[k]) + __bfloat162float(bl[k]));
        P[(size_t)khalf * NN * CC + (size_t)m * CC + c] = acc;
    }
#endif
}

// ---------------- transpose-split: Bt = split(x^T)  (coalesced) --------------
// grid (NN/32, CC/32), block (32, 8)
__global__ void convert_x(const float* __restrict__ x)
{
    __shared__ float tile[32][33];
    const int n0 = blockIdx.x * 32, c0 = blockIdx.y * 32;
    const int tx = threadIdx.x, ty = threadIdx.y;
#pragma unroll
    for (int r = 0; r < 4; r++) {
        int row = ty + 8 * r;
        tile[row][tx] = x[(size_t)(n0 + row) * CC + c0 + tx];
    }
    __syncthreads();
#pragma unroll
    for (int r = 0; r < 4; r++) {
        int crow = ty + 8 * r;
        float v = tile[tx][crow];                    // = x[n0+tx][c0+crow]
        __nv_bfloat16 h = __float2bfloat16(v);
        size_t o = (size_t)(c0 + crow) * NN + n0 + tx;
        g_Bt_hi[o] = h;
        g_Bt_lo[o] = __float2bfloat16(v - __bfloat162float(h));
    }
}

// ---------------- T1 = P0+P1 (coalesced) + transposed split ------------------
__global__ void reduce1()
{
    __shared__ float tile[32][33];
    const int n0 = blockIdx.x * 32, c0 = blockIdx.y * 32;
    const int tx = threadIdx.x, ty = threadIdx.y;
#pragma unroll
    for (int r = 0; r < 4; r++) {
        int row = ty + 8 * r;
        size_t o = (size_t)(n0 + row) * CC + c0 + tx;
        float v = g_P[o] + g_P[(size_t)NN * CC + o];
        g_T1[o] = v;
        tile[row][tx] = v;
    }
    __syncthreads();
#pragma unroll
    for (int r = 0; r < 4; r++) {
        int crow = ty + 8 * r;
        float v = tile[tx][crow];
        __nv_bfloat16 h = __float2bfloat16(v);
        size_t o = (size_t)(c0 + crow) * NN + n0 + tx;
        g_Bt_hi[o] = h;
        g_Bt_lo[o] = __float2bfloat16(v - __bfloat162float(h));
    }
}

// ---- out = x@W0^T + T1@W1^T + T2@W2^T, with T2 = 2*(P0+P1)-x built in smem --
__global__ __launch_bounds__(256)
void cheb_out_fused(const float* __restrict__ x, const float* __restrict__ W,
                    float* __restrict__ out)
{
    const int BK = 16;
    __shared__ float T2s[64][CC];   // 32 KB
    __shared__ float As[BK][64];
    __shared__ float Ws[BK][CC];

    const int tid = threadIdx.x;
    const int tx = tid & 31, ty = tid >> 5;
    const int rowBase = blockIdx.x * 64;

#pragma unroll
    for (int i = 0; i < 8; i++) {
        int f = tid + i * 256;
        int r = f >> 5, cg = f & 31;
        size_t o = (size_t)(rowBase + r) * CC + cg * 4;
        float4 p0 = *(const float4*)(g_P + o);
        float4 p1 = *(const float4*)(g_P + (size_t)NN * CC + o);
        float4 xv = *(const float4*)(x + o);
        T2s[r][cg * 4 + 0] = 2.0f * (p0.x + p1.x) - xv.x;
        T2s[r][cg * 4 + 1] = 2.0f * (p0.y + p1.y) - xv.y;
        T2s[r][cg * 4 + 2] = 2.0f * (p0.z + p1.z) - xv.z;
        T2s[r][cg * 4 + 3] = 2.0f * (p0.w + p1.w) - xv.w;
    }
    __syncthreads();

    float acc[8][4];
#pragma unroll
    for (int i = 0; i < 8; i++)
#pragma unroll
        for (int j = 0; j < 4; j++) acc[i][j] = 0.0f;

    const float* Amats[2] = {x, g_T1};
    for (int jm = 0; jm < 3; jm++) {
        const float* Wj = W + (size_t)jm * CC * CC;
        for (int k0 = 0; k0 < CC; k0 += BK) {
            {
                int r = tid >> 2, cg = tid & 3;
                float4 v;
                if (jm < 2)
                    v = *(const float4*)(Amats[jm] + (size_t)(rowBase + r) * CC + k0 + cg * 4);
                else
                    v = *(const float4*)(&T2s[r][k0 + cg * 4]);
                As[cg * 4 + 0][r] = v.x; As[cg * 4 + 1][r] = v.y;
                As[cg * 4 + 2][r] = v.z; As[cg * 4 + 3][r] = v.w;
            }
#pragma unroll
            for (int i = 0; i < 2; i++) {
                int f = tid * 2 + i;
                int n = f >> 2, cg = f & 3;
                float4 v = *(const float4*)(Wj + (size_t)n * CC + k0 + cg * 4);
                Ws[cg * 4 + 0][n] = v.x; Ws[cg * 4 + 1][n] = v.y;
                Ws[cg * 4 + 2][n] = v.z; Ws[cg * 4 + 3][n] = v.w;
            }
            __syncthreads();
#pragma unroll
            for (int kk = 0; kk < BK; kk++) {
                float4 a0 = *(const float4*)(&As[kk][ty * 8 + 0]);
                float4 a1 = *(const float4*)(&As[kk][ty * 8 + 4]);
                float4 b0 = *(const float4*)(&Ws[kk][tx * 4]);
                float a[8] = {a0.x, a0.y, a0.z, a0.w, a1.x, a1.y, a1.z, a1.w};
                float b[4] = {b0.x, b0.y, b0.z, b0.w};
#pragma unroll
                for (int i = 0; i < 8; i++)
#pragma unroll
                    for (int j = 0; j < 4; j++) acc[i][j] += a[i] * b[j];
            }
            __syncthreads();
        }
    }
#pragma unroll
    for (int i = 0; i < 8; i++) {
        size_t off = (size_t)(rowBase + ty * 8 + i) * CC + tx * 4;
        float4 v = {acc[i][0], acc[i][1], acc[i][2], acc[i][3]};
        *(float4*)(out + off) = v;
    }
}

// ---------------- launch -----------------------------------------------------
extern "C" void kernel_launch(void* const* d_in, const int* in_sizes, int n_in,
                              void* d_out, int out_size)
{
    const float *x = nullptr, *L = nullptr, *W = nullptr;
    for (int i = 0; i < n_in; i++) {
        long long sz = in_sizes[i];
        if (sz == (long long)NN * NN)      L = (const float*)d_in[i];
        else if (sz == 3LL * CC * CC)      W = (const float*)d_in[i];
        else if (sz == (long long)NN * CC) x = (const float*)d_in[i];
    }
    float* out = (float*)d_out;

    void* pP  = nullptr; cudaGetSymbolAddress(&pP,  g_P);
    void* pBh = nullptr; cudaGetSymbolAddress(&pBh, g_Bt_hi);
    void* pBl = nullptr; cudaGetSymbolAddress(&pBl, g_Bt_lo);

    cudaFuncSetAttribute(gemm_tc, cudaFuncAttributeMaxDynamicSharedMemorySize, SMEM_TOTAL);

    dim3 gGemm(64, 2);
    dim3 gTr(NN / 32, CC / 32);
    dim3 bTr(32, 8);

    convert_x<<<gTr, bTr>>>(x);
    gemm_tc<<<gGemm, 544, SMEM_TOTAL>>>(L, (const __nv_bfloat16*)pBh,
                                        (const __nv_bfloat16*)pBl, (float*)pP);
    reduce1<<<gTr, bTr>>>();
    gemm_tc<<<gGemm, 544, SMEM_TOTAL>>>(L, (const __nv_bfloat16*)pBh,
                                        (const __nv_bfloat16*)pBl, (float*)pP);
    cheb_out_fused<<<NN / 64, 256>>>(x, W, out);
}

// round 15
// speedup vs baseline: 1.1635x; 1.1635x over previous
#include <cuda_runtime.h>
#include <cuda_bf16.h>
#include <cstdint>

#define NN 8192
#define CC 128

#if defined(__CUDA_ARCH_FEAT_SM103_ALL) || defined(__CUDA_ARCH_FEAT_SM100_ALL) || defined(__CUDA_ARCH_FEAT_SM101_ALL)
#define HAS_TCGEN05 1
#else
#define HAS_TCGEN05 0
#endif

// ---------------- scratch (__device__ globals: allocation-free rule) --------
__device__ float g_T1[NN * CC];
__device__ float g_P[2 * NN * CC];                 // split-K partials
__device__ float g_Bt[CC * NN];                    // transposed B operand, tf32-rounded fp32

// ---------------- PTX helpers (safe on all targets) -------------------------
__device__ __forceinline__ uint32_t smem_u32(const void* p) {
    uint32_t a;
    asm("{ .reg .u64 t; cvta.to.shared.u64 t, %1; cvt.u32.u64 %0, t; }" : "=r"(a) : "l"(p));
    return a;
}

__device__ __forceinline__ float cvt_tf32(float x) {
    float r;
    asm("cvt.rna.tf32.f32 %0, %1;" : "=f"(r) : "f"(x));
    return r;
}

#define MBARRIER_INIT(addr, cnt) \
    asm volatile("mbarrier.init.shared.b64 [%0], %1;" :: "r"((uint32_t)(addr)), "r"((uint32_t)(cnt)) : "memory")

#define MBARRIER_ARRIVE(addr) \
    asm volatile("mbarrier.arrive.release.cta.shared::cta.b64 _, [%0];" :: "r"((uint32_t)(addr)) : "memory")

#define MBARRIER_WAIT_PARITY(addr, parity) do {                                    \
    uint32_t _m = (uint32_t)(addr), _p = (uint32_t)(parity), _d;                   \
    asm volatile("{\n\t.reg .pred p;\n\t"                                          \
        "mbarrier.try_wait.parity.acquire.cta.shared::cta.b64 p, [%1], %2;\n\t"    \
        "selp.b32 %0, 1, 0, p;\n\t}" : "=r"(_d) : "r"(_m), "r"(_p) : "memory");    \
    if (!_d) {                                                                     \
        asm volatile("{\n\t.reg .pred P1;\n\t"                                     \
            "WL_%=:\n\t"                                                           \
            "mbarrier.try_wait.parity.acquire.cta.shared::cta.b64 P1, [%0], %1, 0x989680;\n\t" \
            "@P1 bra.uni WD_%=;\n\tbra.uni WL_%=;\n\tWD_%=:\n\t}"                  \
            :: "r"(_m), "r"(_p) : "memory");                                       \
    }                                                                              \
} while (0)

#define FENCE_PROXY_ASYNC()    asm volatile("fence.proxy.async.shared::cta;" ::: "memory")

// SW128 descriptor: layout=2, version=1, SBO=64, LBO=1
static constexpr uint64_t DESC_BASE_SW128 =
    (uint64_t(2) << 61) | (uint64_t(1) << 46) | (uint64_t(64) << 32) | (uint64_t(1) << 16);
#define MAKE_DESC(addr) (DESC_BASE_SW128 | ((uint64_t)((addr) >> 4) & 0x3FFF))

__device__ __forceinline__ uint32_t sw128(uint32_t o) { return o ^ ((o >> 3) & 0x70); }

// idesc: fp32 accum, TF32 A/B (format code 2), M=128, N=128
static constexpr uint32_t IDESC_TF32 =
    (1u << 4) | (2u << 7) | (2u << 10) | ((128u / 8) << 17) | ((128u / 16) << 24);

// K-step descriptor offsets (16B units) inside blocked-atom SW128 layout:
// 128 rows x 64 k fp32; atom = 8 rows x 128B; atom_col 1 (k>=32) at 16*1024B.
__device__ static constexpr uint32_t KSTEP_OFF[8] = {0, 2, 4, 6, 1024, 1026, 1028, 1030};

// ---------------- smem layout ------------------------------------------------
// [0] tmem ptr | [16,40) full[3] | [40,88) empty[3][2] | [88,96) done
// [1024+) 3 stages x (A 32K | B 32K)
#define SM_TMEM   0
#define SM_FULL   16
#define SM_EMPTY  40
#define SM_DONE   88
#define SM_TILES  1024
#define STAGE_SZ  65536
#define NSTAGE    3
#define SMEM_TOTAL (SM_TILES + NSTAGE * STAGE_SZ)

// ---------------- tensor-core GEMM: P[khalf] = L[tile] @ Bt^T (tf32) ---------
// grid (64, 2); 544 threads. Warps 0-7 fill EVEN chunks, warps 8-15 ODD chunks,
// warp 16 lane 0 = MMA issuer. Single tf32 product (no hi/lo split).
__global__ __launch_bounds__(544, 1)
void gemm_tc(const float* __restrict__ L,
             const float* __restrict__ Bt,
             float* __restrict__ P)
{
#if HAS_TCGEN05
    extern __shared__ char smem[];
    const uint32_t sbase = smem_u32(smem);
    const int tid = threadIdx.x;
    const int wid = tid >> 5, lid = tid & 31;
    const int mBase = blockIdx.x * 128;
    const int khalf = blockIdx.y;
    const int kStart = khalf * 4096;
    const int NCHUNK = 4096 / 64;

    if (wid == 0)
        asm volatile("tcgen05.alloc.cta_group::1.sync.aligned.shared::cta.b32 [%0], %1;"
                     :: "r"(sbase + SM_TMEM), "r"(128u) : "memory");
    if (tid == 0) {
#pragma unroll
        for (int s = 0; s < NSTAGE; s++) {
            MBARRIER_INIT(sbase + SM_FULL + 8 * s, 8);              // 8 warps per filling group
            MBARRIER_INIT(sbase + SM_EMPTY + 16 * s + 0, 1);        // empty[s][g=0]
            MBARRIER_INIT(sbase + SM_EMPTY + 16 * s + 8, 1);        // empty[s][g=1]
        }
        MBARRIER_INIT(sbase + SM_DONE, 1);
    }
    __syncthreads();
    uint32_t tmem;
    asm volatile("ld.shared.b32 %0, [%1];" : "=r"(tmem) : "r"(sbase + SM_TMEM));

    if (wid < 16) {
        // ---------------- producers: group g fills chunks c ≡ g (mod 2) ------
        const int g = (tid >> 8) & 1;            // warps 0-7 -> g=0, 8-15 -> g=1
        const int p = tid & 255;                 // 0..255 within group
        int phE[NSTAGE] = {0, 0, 0};

        // per-thread tile coords: 2048 16B-units = 128 rows x 16 cols(16B).
        // unit u = p + 256*i -> row = (p>>4)+16*i (col constant = p&15).
        const int row0 = p >> 4;                 // 0..15
        const int col  = p & 15;                 // 16B column (4 fp32)
        // blocked-atom swizzled offsets (same layout for A and B tiles)
        uint32_t off[8];
#pragma unroll
        for (int i = 0; i < 8; i++) {
            int row = row0 + 16 * i;
            uint32_t byte = (uint32_t)(((row >> 3) + (col >> 3) * 16) * 1024
                                       + (row & 7) * 128 + (col & 7) * 16);
            off[i] = sw128(byte);
        }
        const float* aBase = L + (size_t)(mBase + row0) * NN + kStart + col * 4;
        const float* bBase = Bt + (size_t)row0 * NN + kStart + col * 4;

        for (int j = 0; j < NCHUNK / 2; j++) {
            const int c = 2 * j + g;
            const int s = c % 3;
            const uint32_t stg = sbase + SM_TILES + s * STAGE_SZ;
            char* stgp = smem + SM_TILES + s * STAGE_SZ;
            const int kOff = c * 64;

            // stage previously used by chunk c-3 -> wait its MMA completion
            if (c >= 3) { MBARRIER_WAIT_PARITY(sbase + SM_EMPTY + 16 * s + 8 * g, phE[s]); phE[s] ^= 1; }

            // B: pre-rounded tf32 fp32 via cp.async (8 x 16B per thread)
#pragma unroll
            for (int i = 0; i < 8; i++) {
                asm volatile("cp.async.cg.shared.global [%0], [%1], 16;"
                             :: "r"(stg + 32768 + off[i]),
                                "l"(bBase + (size_t)(16 * i) * NN + kOff) : "memory");
            }
            asm volatile("cp.async.commit_group;" ::: "memory");

            // A: batch 8 float4 loads, then rna-round to tf32 + store
            float4 va[8];
#pragma unroll
            for (int i = 0; i < 8; i++)
                va[i] = *(const float4*)(aBase + (size_t)(16 * i) * NN + kOff);
#pragma unroll
            for (int i = 0; i < 8; i++) {
                float4 t;
                t.x = cvt_tf32(va[i].x);
                t.y = cvt_tf32(va[i].y);
                t.z = cvt_tf32(va[i].z);
                t.w = cvt_tf32(va[i].w);
                *(float4*)(stgp + off[i]) = t;
            }
            asm volatile("cp.async.wait_group 0;" ::: "memory");
            __syncwarp();
            if (lid == 0) MBARRIER_ARRIVE(sbase + SM_FULL + 8 * s);
        }
    } else if (lid == 0) {
        // ---------------- MMA issuer (warp 16, lane 0) -----------------------
        int phF[NSTAGE] = {0, 0, 0};
        for (int c = 0; c < NCHUNK; c++) {
            const int s = c % 3;
            MBARRIER_WAIT_PARITY(sbase + SM_FULL + 8 * s, phF[s]);
            phF[s] ^= 1;
            FENCE_PROXY_ASYNC();
            const uint32_t stg = sbase + SM_TILES + s * STAGE_SZ;
            uint64_t dA = MAKE_DESC(stg);
            uint64_t dB = MAKE_DESC(stg + 32768);
#pragma unroll
            for (int ks = 0; ks < 8; ks++) {
                uint32_t en = (c > 0 || ks > 0) ? 1u : 0u;
                asm volatile(
                    "{\n\t.reg .pred p;\n\tsetp.ne.u32 p, %5, 0;\n\t"
                    "tcgen05.mma.cta_group::1.kind::tf32 [%0], %1, %2, %3, {%4,%4,%4,%4}, p;\n\t}"
                    :: "r"(tmem), "l"(dA + KSTEP_OFF[ks]), "l"(dB + KSTEP_OFF[ks]),
                       "r"(IDESC_TF32), "r"(0u), "r"(en) : "memory");
            }
            // stage s is next filled by chunk c+3 (group (c+1)&1)
            asm volatile("tcgen05.commit.cta_group::1.mbarrier::arrive::one.shared::cluster.b64 [%0];"
                         :: "r"(sbase + SM_EMPTY + 16 * s + 8 * ((c + 1) & 1)) : "memory");
        }
        asm volatile("tcgen05.commit.cta_group::1.mbarrier::arrive::one.shared::cluster.b64 [%0];"
                     :: "r"(sbase + SM_DONE) : "memory");
    }

    // all threads: wait for full completion
    MBARRIER_WAIT_PARITY(sbase + SM_DONE, 0);
    asm volatile("tcgen05.fence::after_thread_sync;" ::: "memory");

    // epilogue: warps 0-3 read subpartitions (128 rows x 128 fp32 cols)
    if (wid < 4) {
        const int m = mBase + wid * 32 + lid;
        float* dst = P + (size_t)khalf * NN * CC + (size_t)m * CC;
#pragma unroll
        for (int cb = 0; cb < 128; cb += 32) {
            uint32_t r[32];
            asm volatile("tcgen05.ld.sync.aligned.32x32b.x32.b32 "
                "{%0,%1,%2,%3,%4,%5,%6,%7,%8,%9,%10,%11,%12,%13,%14,%15,"
                "%16,%17,%18,%19,%20,%21,%22,%23,%24,%25,%26,%27,%28,%29,%30,%31}, [%32];"
                : "=r"(r[0]),"=r"(r[1]),"=r"(r[2]),"=r"(r[3]),"=r"(r[4]),"=r"(r[5]),"=r"(r[6]),"=r"(r[7]),
                  "=r"(r[8]),"=r"(r[9]),"=r"(r[10]),"=r"(r[11]),"=r"(r[12]),"=r"(r[13]),"=r"(r[14]),"=r"(r[15]),
                  "=r"(r[16]),"=r"(r[17]),"=r"(r[18]),"=r"(r[19]),"=r"(r[20]),"=r"(r[21]),"=r"(r[22]),"=r"(r[23]),
                  "=r"(r[24]),"=r"(r[25]),"=r"(r[26]),"=r"(r[27]),"=r"(r[28]),"=r"(r[29]),"=r"(r[30]),"=r"(r[31])
                : "r"(tmem + cb));
            asm volatile("tcgen05.wait::ld.sync.aligned;" ::: "memory");
#pragma unroll
            for (int j = 0; j < 32; j += 4) {
                float4 v = { __uint_as_float(r[j]), __uint_as_float(r[j + 1]),
                             __uint_as_float(r[j + 2]), __uint_as_float(r[j + 3]) };
                *(float4*)(dst + cb + j) = v;
            }
        }
        asm volatile("tcgen05.fence::before_thread_sync;" ::: "memory");
    }
    __syncthreads();
    if (wid == 0) {
        asm volatile("tcgen05.relinquish_alloc_permit.cta_group::1.sync.aligned;");
        asm volatile("tcgen05.dealloc.cta_group::1.sync.aligned.b32 %0, %1;" :: "r"(tmem), "r"(128u));
    }
#else
    // Fallback for the non-'a' PTX pass (never executed on GB300).
    const int tid = threadIdx.x;
    const int mBase = blockIdx.x * 128;
    const int khalf = blockIdx.y;
    const int kStart = khalf * 4096;
    for (int e = tid; e < 128 * 128; e += 544) {
        int m = mBase + (e >> 7), c = e & 127;
        float acc = 0.0f;
        const float* Lr = L + (size_t)m * NN + kStart;
        const float* br = Bt + (size_t)c * NN + kStart;
        for (int k = 0; k < 4096; k++) acc += Lr[k] * br[k];
        P[(size_t)khalf * NN * CC + (size_t)m * CC + c] = acc;
    }
#endif
}

// ---------------- transpose: Bt = tf32(x^T)  (coalesced) ---------------------
// grid (NN/32, CC/32), block (32, 8)
__global__ void convert_x(const float* __restrict__ x)
{
    __shared__ float tile[32][33];
    const int n0 = blockIdx.x * 32, c0 = blockIdx.y * 32;
    const int tx = threadIdx.x, ty = threadIdx.y;
#pragma unroll
    for (int r = 0; r < 4; r++) {
        int row = ty + 8 * r;
        tile[row][tx] = x[(size_t)(n0 + row) * CC + c0 + tx];
    }
    __syncthreads();
#pragma unroll
    for (int r = 0; r < 4; r++) {
        int crow = ty + 8 * r;
        g_Bt[(size_t)(c0 + crow) * NN + n0 + tx] = cvt_tf32(tile[tx][crow]);
    }
}

// ---------------- T1 = P0+P1 (coalesced) + transposed tf32 -------------------
__global__ void reduce1()
{
    __shared__ float tile[32][33];
    const int n0 = blockIdx.x * 32, c0 = blockIdx.y * 32;
    const int tx = threadIdx.x, ty = threadIdx.y;
#pragma unroll
    for (int r = 0; r < 4; r++) {
        int row = ty + 8 * r;
        size_t o = (size_t)(n0 + row) * CC + c0 + tx;
        float v = g_P[o] + g_P[(size_t)NN * CC + o];
        g_T1[o] = v;
        tile[row][tx] = v;
    }
    __syncthreads();
#pragma unroll
    for (int r = 0; r < 4; r++) {
        int crow = ty + 8 * r;
        g_Bt[(size_t)(c0 + crow) * NN + n0 + tx] = cvt_tf32(tile[tx][crow]);
    }
}

// ---- out = x@W0^T + T1@W1^T + T2@W2^T, with T2 = 2*(P0+P1)-x built in smem --
__global__ __launch_bounds__(256)
void cheb_out_fused(const float* __restrict__ x, const float* __restrict__ W,
                    float* __restrict__ out)
{
    const int BK = 16;
    __shared__ float T2s[64][CC];   // 32 KB
    __shared__ float As[BK][64];
    __shared__ float Ws[BK][CC];

    const int tid = threadIdx.x;
    const int tx = tid & 31, ty = tid >> 5;
    const int rowBase = blockIdx.x * 64;

#pragma unroll
    for (int i = 0; i < 8; i++) {
        int f = tid + i * 256;
        int r = f >> 5, cg = f & 31;
        size_t o = (size_t)(rowBase + r) * CC + cg * 4;
        float4 p0 = *(const float4*)(g_P + o);
        float4 p1 = *(const float4*)(g_P + (size_t)NN * CC + o);
        float4 xv = *(const float4*)(x + o);
        T2s[r][cg * 4 + 0] = 2.0f * (p0.x + p1.x) - xv.x;
        T2s[r][cg * 4 + 1] = 2.0f * (p0.y + p1.y) - xv.y;
        T2s[r][cg * 4 + 2] = 2.0f * (p0.z + p1.z) - xv.z;
        T2s[r][cg * 4 + 3] = 2.0f * (p0.w + p1.w) - xv.w;
    }
    __syncthreads();

    float acc[8][4];
#pragma unroll
    for (int i = 0; i < 8; i++)
#pragma unroll
        for (int j = 0; j < 4; j++) acc[i][j] = 0.0f;

    const float* Amats[2] = {x, g_T1};
    for (int jm = 0; jm < 3; jm++) {
        const float* Wj = W + (size_t)jm * CC * CC;
        for (int k0 = 0; k0 < CC; k0 += BK) {
            {
                int r = tid >> 2, cg = tid & 3;
                float4 v;
                if (jm < 2)
                    v = *(const float4*)(Amats[jm] + (size_t)(rowBase + r) * CC + k0 + cg * 4);
                else
                    v = *(const float4*)(&T2s[r][k0 + cg * 4]);
                As[cg * 4 + 0][r] = v.x; As[cg * 4 + 1][r] = v.y;
                As[cg * 4 + 2][r] = v.z; As[cg * 4 + 3][r] = v.w;
            }
#pragma unroll
            for (int i = 0; i < 2; i++) {
                int f = tid * 2 + i;
                int n = f >> 2, cg = f & 3;
                float4 v = *(const float4*)(Wj + (size_t)n * CC + k0 + cg * 4);
                Ws[cg * 4 + 0][n] = v.x; Ws[cg * 4 + 1][n] = v.y;
                Ws[cg * 4 + 2][n] = v.z; Ws[cg * 4 + 3][n] = v.w;
            }
            __syncthreads();
#pragma unroll
            for (int kk = 0; kk < BK; kk++) {
                float4 a0 = *(const float4*)(&As[kk][ty * 8 + 0]);
                float4 a1 = *(const float4*)(&As[kk][ty * 8 + 4]);
                float4 b0 = *(const float4*)(&Ws[kk][tx * 4]);
                float a[8] = {a0.x, a0.y, a0.z, a0.w, a1.x, a1.y, a1.z, a1.w};
                float b[4] = {b0.x, b0.y, b0.z, b0.w};
#pragma unroll
                for (int i = 0; i < 8; i++)
#pragma unroll
                    for (int j = 0; j < 4; j++) acc[i][j] += a[i] * b[j];
            }
            __syncthreads();
        }
    }
#pragma unroll
    for (int i = 0; i < 8; i++) {
        size_t off = (size_t)(rowBase + ty * 8 + i) * CC + tx * 4;
        float4 v = {acc[i][0], acc[i][1], acc[i][2], acc[i][3]};
        *(float4*)(out + off) = v;
    }
}

// ---------------- launch -----------------------------------------------------
extern "C" void kernel_launch(void* const* d_in, const int* in_sizes, int n_in,
                              void* d_out, int out_size)
{
    const float *x = nullptr, *L = nullptr, *W = nullptr;
    for (int i = 0; i < n_in; i++) {
        long long sz = in_sizes[i];
        if (sz == (long long)NN * NN)      L = (const float*)d_in[i];
        else if (sz == 3LL * CC * CC)      W = (const float*)d_in[i];
        else if (sz == (long long)NN * CC) x = (const float*)d_in[i];
    }
    float* out = (float*)d_out;

    void* pP  = nullptr; cudaGetSymbolAddress(&pP,  g_P);
    void* pBt = nullptr; cudaGetSymbolAddress(&pBt, g_Bt);

    cudaFuncSetAttribute(gemm_tc, cudaFuncAttributeMaxDynamicSharedMemorySize, SMEM_TOTAL);

    dim3 gGemm(64, 2);
    dim3 gTr(NN / 32, CC / 32);
    dim3 bTr(32, 8);

    convert_x<<<gTr, bTr>>>(x);
    gemm_tc<<<gGemm, 544, SMEM_TOTAL>>>(L, (const float*)pBt, (float*)pP);
    reduce1<<<gTr, bTr>>>();
    gemm_tc<<<gGemm, 544, SMEM_TOTAL>>>(L, (const float*)pBt, (float*)pP);
    cheb_out_fused<<<NN / 64, 256>>>(x, W, out);
}

// round 16
// speedup vs baseline: 1.2430x; 1.0683x over previous
#include <cuda_runtime.h>
#include <cuda_bf16.h>
#include <cstdint>

#define NN 8192
#define CC 128

#if defined(__CUDA_ARCH_FEAT_SM103_ALL) || defined(__CUDA_ARCH_FEAT_SM100_ALL) || defined(__CUDA_ARCH_FEAT_SM101_ALL)
#define HAS_TCGEN05 1
#else
#define HAS_TCGEN05 0
#endif

// ---------------- scratch (__device__ globals: allocation-free rule) --------
__device__ float g_T1[NN * CC];
__device__ float g_P[2 * NN * CC];                 // split-K partials
__device__ float g_Bt[CC * NN];                    // transposed B operand, tf32-rounded fp32

// ---------------- PTX helpers (safe on all targets) -------------------------
__device__ __forceinline__ uint32_t smem_u32(const void* p) {
    uint32_t a;
    asm("{ .reg .u64 t; cvta.to.shared.u64 t, %1; cvt.u32.u64 %0, t; }" : "=r"(a) : "l"(p));
    return a;
}

__device__ __forceinline__ float cvt_tf32(float x) {
    float r;
    asm("cvt.rna.tf32.f32 %0, %1;" : "=f"(r) : "f"(x));
    return r;
}

#define MBARRIER_INIT(addr, cnt) \
    asm volatile("mbarrier.init.shared.b64 [%0], %1;" :: "r"((uint32_t)(addr)), "r"((uint32_t)(cnt)) : "memory")

#define MBARRIER_ARRIVE(addr) \
    asm volatile("mbarrier.arrive.release.cta.shared::cta.b64 _, [%0];" :: "r"((uint32_t)(addr)) : "memory")

#define MBARRIER_WAIT_PARITY(addr, parity) do {                                    \
    uint32_t _m = (uint32_t)(addr), _p = (uint32_t)(parity), _d;                   \
    asm volatile("{\n\t.reg .pred p;\n\t"                                          \
        "mbarrier.try_wait.parity.acquire.cta.shared::cta.b64 p, [%1], %2;\n\t"    \
        "selp.b32 %0, 1, 0, p;\n\t}" : "=r"(_d) : "r"(_m), "r"(_p) : "memory");    \
    if (!_d) {                                                                     \
        asm volatile("{\n\t.reg .pred P1;\n\t"                                     \
            "WL_%=:\n\t"                                                           \
            "mbarrier.try_wait.parity.acquire.cta.shared::cta.b64 P1, [%0], %1, 0x989680;\n\t" \
            "@P1 bra.uni WD_%=;\n\tbra.uni WL_%=;\n\tWD_%=:\n\t}"                  \
            :: "r"(_m), "r"(_p) : "memory");                                       \
    }                                                                              \
} while (0)

#define FENCE_PROXY_ASYNC()    asm volatile("fence.proxy.async.shared::cta;" ::: "memory")

// SW128 descriptor: layout=2, version=1, SBO=64, LBO=1
static constexpr uint64_t DESC_BASE_SW128 =
    (uint64_t(2) << 61) | (uint64_t(1) << 46) | (uint64_t(64) << 32) | (uint64_t(1) << 16);
#define MAKE_DESC(addr) (DESC_BASE_SW128 | ((uint64_t)((addr) >> 4) & 0x3FFF))

__device__ __forceinline__ uint32_t sw128(uint32_t o) { return o ^ ((o >> 3) & 0x70); }

// idesc: fp32 accum, TF32 A/B (format code 2), M=128, N=128
static constexpr uint32_t IDESC_TF32 =
    (1u << 4) | (2u << 7) | (2u << 10) | ((128u / 8) << 17) | ((128u / 16) << 24);

// K-step descriptor offsets (16B units) inside blocked-atom SW128 layout:
// 128 rows x 64 k fp32; atom = 8 rows x 128B; atom_col 1 (k>=32) at 16*1024B.
__device__ static constexpr uint32_t KSTEP_OFF[8] = {0, 2, 4, 6, 1024, 1026, 1028, 1030};

// ---------------- smem layout ------------------------------------------------
// [0] tmem ptr | [16,40) full[3] | [40,88) empty[3][2] | [88,96) done
// [1024+) 3 stages x (A 32K | B 32K)
#define SM_TMEM   0
#define SM_FULL   16
#define SM_EMPTY  40
#define SM_DONE   88
#define SM_TILES  1024
#define STAGE_SZ  65536
#define NSTAGE    3
#define SMEM_TOTAL (SM_TILES + NSTAGE * STAGE_SZ)

// ---------------- tensor-core GEMM: P[khalf] = L[tile] @ Bt^T (tf32) ---------
// grid (64, 2); 544 threads. Warps 0-7 fill EVEN chunks, warps 8-15 ODD chunks,
// warp 16 lane 0 = MMA issuer. A streams via cp.async directly (tensor core
// ignores the low 13 mantissa bits of tf32 operands -> no explicit cvt needed).
__global__ __launch_bounds__(544, 1)
void gemm_tc(const float* __restrict__ L,
             const float* __restrict__ Bt,
             float* __restrict__ P)
{
#if HAS_TCGEN05
    extern __shared__ char smem[];
    const uint32_t sbase = smem_u32(smem);
    const int tid = threadIdx.x;
    const int wid = tid >> 5, lid = tid & 31;
    const int mBase = blockIdx.x * 128;
    const int khalf = blockIdx.y;
    const int kStart = khalf * 4096;
    const int NCHUNK = 4096 / 64;

    if (wid == 0)
        asm volatile("tcgen05.alloc.cta_group::1.sync.aligned.shared::cta.b32 [%0], %1;"
                     :: "r"(sbase + SM_TMEM), "r"(128u) : "memory");
    if (tid == 0) {
#pragma unroll
        for (int s = 0; s < NSTAGE; s++) {
            MBARRIER_INIT(sbase + SM_FULL + 8 * s, 8);              // 8 warps per filling group
            MBARRIER_INIT(sbase + SM_EMPTY + 16 * s + 0, 1);        // empty[s][g=0]
            MBARRIER_INIT(sbase + SM_EMPTY + 16 * s + 8, 1);        // empty[s][g=1]
        }
        MBARRIER_INIT(sbase + SM_DONE, 1);
    }
    __syncthreads();
    uint32_t tmem;
    asm volatile("ld.shared.b32 %0, [%1];" : "=r"(tmem) : "r"(sbase + SM_TMEM));

    if (wid < 16) {
        // ---------------- producers: group g fills chunks c ≡ g (mod 2) ------
        const int g = (tid >> 8) & 1;            // warps 0-7 -> g=0, 8-15 -> g=1
        const int p = tid & 255;                 // 0..255 within group
        int phE[NSTAGE] = {0, 0, 0};

        // per-thread tile coords: 2048 16B-units = 128 rows x 16 cols(16B).
        const int row0 = p >> 4;                 // 0..15
        const int col  = p & 15;                 // 16B column (4 fp32)
        uint32_t off[8];
#pragma unroll
        for (int i = 0; i < 8; i++) {
            int row = row0 + 16 * i;
            uint32_t byte = (uint32_t)(((row >> 3) + (col >> 3) * 16) * 1024
                                       + (row & 7) * 128 + (col & 7) * 16);
            off[i] = sw128(byte);
        }
        const float* aBase = L + (size_t)(mBase + row0) * NN + kStart + col * 4;
        const float* bBase = Bt + (size_t)row0 * NN + kStart + col * 4;

        for (int j = 0; j < NCHUNK / 2; j++) {
            const int c = 2 * j + g;
            const int s = c % 3;
            const uint32_t stg = sbase + SM_TILES + s * STAGE_SZ;
            const int kOff = c * 64;

            // stage previously used by chunk c-3 -> wait its MMA completion
            if (c >= 3) { MBARRIER_WAIT_PARITY(sbase + SM_EMPTY + 16 * s + 8 * g, phE[s]); phE[s] ^= 1; }

            // A and B both stream via cp.async (8 x 16B each per thread)
#pragma unroll
            for (int i = 0; i < 8; i++) {
                asm volatile("cp.async.cg.shared.global [%0], [%1], 16;"
                             :: "r"(stg + off[i]),
                                "l"(aBase + (size_t)(16 * i) * NN + kOff) : "memory");
                asm volatile("cp.async.cg.shared.global [%0], [%1], 16;"
                             :: "r"(stg + 32768 + off[i]),
                                "l"(bBase + (size_t)(16 * i) * NN + kOff) : "memory");
            }
            asm volatile("cp.async.commit_group;" ::: "memory");
            asm volatile("cp.async.wait_group 0;" ::: "memory");
            __syncwarp();
            if (lid == 0) MBARRIER_ARRIVE(sbase + SM_FULL + 8 * s);
        }
    } else if (lid == 0) {
        // ---------------- MMA issuer (warp 16, lane 0) -----------------------
        int phF[NSTAGE] = {0, 0, 0};
        for (int c = 0; c < NCHUNK; c++) {
            const int s = c % 3;
            MBARRIER_WAIT_PARITY(sbase + SM_FULL + 8 * s, phF[s]);
            phF[s] ^= 1;
            FENCE_PROXY_ASYNC();
            const uint32_t stg = sbase + SM_TILES + s * STAGE_SZ;
            uint64_t dA = MAKE_DESC(stg);
            uint64_t dB = MAKE_DESC(stg + 32768);
#pragma unroll
            for (int ks = 0; ks < 8; ks++) {
                uint32_t en = (c > 0 || ks > 0) ? 1u : 0u;
                asm volatile(
                    "{\n\t.reg .pred p;\n\tsetp.ne.u32 p, %5, 0;\n\t"
                    "tcgen05.mma.cta_group::1.kind::tf32 [%0], %1, %2, %3, {%4,%4,%4,%4}, p;\n\t}"
                    :: "r"(tmem), "l"(dA + KSTEP_OFF[ks]), "l"(dB + KSTEP_OFF[ks]),
                       "r"(IDESC_TF32), "r"(0u), "r"(en) : "memory");
            }
            // stage s is next filled by chunk c+3 (group (c+1)&1)
            asm volatile("tcgen05.commit.cta_group::1.mbarrier::arrive::one.shared::cluster.b64 [%0];"
                         :: "r"(sbase + SM_EMPTY + 16 * s + 8 * ((c + 1) & 1)) : "memory");
        }
        asm volatile("tcgen05.commit.cta_group::1.mbarrier::arrive::one.shared::cluster.b64 [%0];"
                     :: "r"(sbase + SM_DONE) : "memory");
    }

    // all threads: wait for full completion
    MBARRIER_WAIT_PARITY(sbase + SM_DONE, 0);
    asm volatile("tcgen05.fence::after_thread_sync;" ::: "memory");

    // epilogue: warps 0-3 read subpartitions (128 rows x 128 fp32 cols)
    if (wid < 4) {
        const int m = mBase + wid * 32 + lid;
        float* dst = P + (size_t)khalf * NN * CC + (size_t)m * CC;
#pragma unroll
        for (int cb = 0; cb < 128; cb += 32) {
            uint32_t r[32];
            asm volatile("tcgen05.ld.sync.aligned.32x32b.x32.b32 "
                "{%0,%1,%2,%3,%4,%5,%6,%7,%8,%9,%10,%11,%12,%13,%14,%15,"
                "%16,%17,%18,%19,%20,%21,%22,%23,%24,%25,%26,%27,%28,%29,%30,%31}, [%32];"
                : "=r"(r[0]),"=r"(r[1]),"=r"(r[2]),"=r"(r[3]),"=r"(r[4]),"=r"(r[5]),"=r"(r[6]),"=r"(r[7]),
                  "=r"(r[8]),"=r"(r[9]),"=r"(r[10]),"=r"(r[11]),"=r"(r[12]),"=r"(r[13]),"=r"(r[14]),"=r"(r[15]),
                  "=r"(r[16]),"=r"(r[17]),"=r"(r[18]),"=r"(r[19]),"=r"(r[20]),"=r"(r[21]),"=r"(r[22]),"=r"(r[23]),
                  "=r"(r[24]),"=r"(r[25]),"=r"(r[26]),"=r"(r[27]),"=r"(r[28]),"=r"(r[29]),"=r"(r[30]),"=r"(r[31])
                : "r"(tmem + cb));
            asm volatile("tcgen05.wait::ld.sync.aligned;" ::: "memory");
#pragma unroll
            for (int j = 0; j < 32; j += 4) {
                float4 v = { __uint_as_float(r[j]), __uint_as_float(r[j + 1]),
                             __uint_as_float(r[j + 2]), __uint_as_float(r[j + 3]) };
                *(float4*)(dst + cb + j) = v;
            }
        }
        asm volatile("tcgen05.fence::before_thread_sync;" ::: "memory");
    }
    __syncthreads();
    if (wid == 0) {
        asm volatile("tcgen05.relinquish_alloc_permit.cta_group::1.sync.aligned;");
        asm volatile("tcgen05.dealloc.cta_group::1.sync.aligned.b32 %0, %1;" :: "r"(tmem), "r"(128u));
    }
#else
    // Fallback for the non-'a' PTX pass (never executed on GB300).
    const int tid = threadIdx.x;
    const int mBase = blockIdx.x * 128;
    const int khalf = blockIdx.y;
    const int kStart = khalf * 4096;
    for (int e = tid; e < 128 * 128; e += 544) {
        int m = mBase + (e >> 7), c = e & 127;
        float acc = 0.0f;
        const float* Lr = L + (size_t)m * NN + kStart;
        const float* br = Bt + (size_t)c * NN + kStart;
        for (int k = 0; k < 4096; k++) acc += Lr[k] * br[k];
        P[(size_t)khalf * NN * CC + (size_t)m * CC + c] = acc;
    }
#endif
}

// ---------------- transpose: Bt = tf32(x^T)  (coalesced) ---------------------
// grid (NN/32, CC/32), block (32, 8)
__global__ void convert_x(const float* __restrict__ x)
{
    __shared__ float tile[32][33];
    const int n0 = blockIdx.x * 32, c0 = blockIdx.y * 32;
    const int tx = threadIdx.x, ty = threadIdx.y;
#pragma unroll
    for (int r = 0; r < 4; r++) {
        int row = ty + 8 * r;
        tile[row][tx] = x[(size_t)(n0 + row) * CC + c0 + tx];
    }
    __syncthreads();
#pragma unroll
    for (int r = 0; r < 4; r++) {
        int crow = ty + 8 * r;
        g_Bt[(size_t)(c0 + crow) * NN + n0 + tx] = cvt_tf32(tile[tx][crow]);
    }
}

// ---------------- T1 = P0+P1 (coalesced) + transposed tf32 -------------------
__global__ void reduce1()
{
    __shared__ float tile[32][33];
    const int n0 = blockIdx.x * 32, c0 = blockIdx.y * 32;
    const int tx = threadIdx.x, ty = threadIdx.y;
#pragma unroll
    for (int r = 0; r < 4; r++) {
        int row = ty + 8 * r;
        size_t o = (size_t)(n0 + row) * CC + c0 + tx;
        float v = g_P[o] + g_P[(size_t)NN * CC + o];
        g_T1[o] = v;
        tile[row][tx] = v;
    }
    __syncthreads();
#pragma unroll
    for (int r = 0; r < 4; r++) {
        int crow = ty + 8 * r;
        g_Bt[(size_t)(c0 + crow) * NN + n0 + tx] = cvt_tf32(tile[tx][crow]);
    }
}

// ---- out = x@W0^T + T1@W1^T + T2@W2^T, with T2 = 2*(P0+P1)-x built in smem --
__global__ __launch_bounds__(256)
void cheb_out_fused(const float* __restrict__ x, const float* __restrict__ W,
                    float* __restrict__ out)
{
    const int BK = 16;
    __shared__ float T2s[64][CC];   // 32 KB
    __shared__ float As[BK][64];
    __shared__ float Ws[BK][CC];

    const int tid = threadIdx.x;
    const int tx = tid & 31, ty = tid >> 5;
    const int rowBase = blockIdx.x * 64;

#pragma unroll
    for (int i = 0; i < 8; i++) {
        int f = tid + i * 256;
        int r = f >> 5, cg = f & 31;
        size_t o = (size_t)(rowBase + r) * CC + cg * 4;
        float4 p0 = *(const float4*)(g_P + o);
        float4 p1 = *(const float4*)(g_P + (size_t)NN * CC + o);
        float4 xv = *(const float4*)(x + o);
        T2s[r][cg * 4 + 0] = 2.0f * (p0.x + p1.x) - xv.x;
        T2s[r][cg * 4 + 1] = 2.0f * (p0.y + p1.y) - xv.y;
        T2s[r][cg * 4 + 2] = 2.0f * (p0.z + p1.z) - xv.z;
        T2s[r][cg * 4 + 3] = 2.0f * (p0.w + p1.w) - xv.w;
    }
    __syncthreads();

    float acc[8][4];
#pragma unroll
    for (int i = 0; i < 8; i++)
#pragma unroll
        for (int j = 0; j < 4; j++) acc[i][j] = 0.0f;

    const float* Amats[2] = {x, g_T1};
    for (int jm = 0; jm < 3; jm++) {
        const float* Wj = W + (size_t)jm * CC * CC;
        for (int k0 = 0; k0 < CC; k0 += BK) {
            {
                int r = tid >> 2, cg = tid & 3;
                float4 v;
                if (jm < 2)
                    v = *(const float4*)(Amats[jm] + (size_t)(rowBase + r) * CC + k0 + cg * 4);
                else
                    v = *(const float4*)(&T2s[r][k0 + cg * 4]);
                As[cg * 4 + 0][r] = v.x; As[cg * 4 + 1][r] = v.y;
                As[cg * 4 + 2][r] = v.z; As[cg * 4 + 3][r] = v.w;
            }
#pragma unroll
            for (int i = 0; i < 2; i++) {
                int f = tid * 2 + i;
                int n = f >> 2, cg = f & 3;
                float4 v = *(const float4*)(Wj + (size_t)n * CC + k0 + cg * 4);
                Ws[cg * 4 + 0][n] = v.x; Ws[cg * 4 + 1][n] = v.y;
                Ws[cg * 4 + 2][n] = v.z; Ws[cg * 4 + 3][n] = v.w;
            }
            __syncthreads();
#pragma unroll
            for (int kk = 0; kk < BK; kk++) {
                float4 a0 = *(const float4*)(&As[kk][ty * 8 + 0]);
                float4 a1 = *(const float4*)(&As[kk][ty * 8 + 4]);
                float4 b0 = *(const float4*)(&Ws[kk][tx * 4]);
                float a[8] = {a0.x, a0.y, a0.z, a0.w, a1.x, a1.y, a1.z, a1.w};
                float b[4] = {b0.x, b0.y, b0.z, b0.w};
#pragma unroll
                for (int i = 0; i < 8; i++)
#pragma unroll
                    for (int j = 0; j < 4; j++) acc[i][j] += a[i] * b[j];
            }
            __syncthreads();
        }
    }
#pragma unroll
    for (int i = 0; i < 8; i++) {
        size_t off = (size_t)(rowBase + ty * 8 + i) * CC + tx * 4;
        float4 v = {acc[i][0], acc[i][1], acc[i][2], acc[i][3]};
        *(float4*)(out + off) = v;
    }
}

// ---------------- launch -----------------------------------------------------
extern "C" void kernel_launch(void* const* d_in, const int* in_sizes, int n_in,
                              void* d_out, int out_size)
{
    const float *x = nullptr, *L = nullptr, *W = nullptr;
    for (int i = 0; i < n_in; i++) {
        long long sz = in_sizes[i];
        if (sz == (long long)NN * NN)      L = (const float*)d_in[i];
        else if (sz == 3LL * CC * CC)      W = (const float*)d_in[i];
        else if (sz == (long long)NN * CC) x = (const float*)d_in[i];
    }
    float* out = (float*)d_out;

    void* pP  = nullptr; cudaGetSymbolAddress(&pP,  g_P);
    void* pBt = nullptr; cudaGetSymbolAddress(&pBt, g_Bt);

    cudaFuncSetAttribute(gemm_tc, cudaFuncAttributeMaxDynamicSharedMemorySize, SMEM_TOTAL);

    dim3 gGemm(64, 2);
    dim3 gTr(NN / 32, CC / 32);
    dim3 bTr(32, 8);

    convert_x<<<gTr, bTr>>>(x);
    gemm_tc<<<gGemm, 544, SMEM_TOTAL>>>(L, (const float*)pBt, (float*)pP);
    reduce1<<<gTr, bTr>>>();
    gemm_tc<<<gGemm, 544, SMEM_TOTAL>>>(L, (const float*)pBt, (float*)pP);
    cheb_out_fused<<<NN / 64, 256>>>(x, W, out);
}